// round 6
// baseline (speedup 1.0000x reference)
#include <cuda_runtime.h>
#include <math.h>

// Problem constants
#define N_BATCH 64
#define C_FULL  256
#define P_CH    64
#define HW      32
#define SPAT    1024            // 32*32
#define E_TOT   10
#define STATE_SZ (N_BATCH * C_FULL * SPAT)   // 16,777,216 floats

// Persistent device scratch (no allocation allowed in kernel_launch)
__device__ float g_state[3][STATE_SZ];            // states 1..3 (state 4 -> d_out)
__device__ float g_keff[E_TOT][P_CH][81][P_CH];   // [e][ci][tap][co]
__device__ float g_w[E_TOT][12];                  // softmaxed arch weights

// ---------------------------------------------------------------------------
// Kernel 1: softmax of arch params per edge
// ---------------------------------------------------------------------------
__global__ void softmax_kernel(const float* __restrict__ ap,
                               const float* __restrict__ en) {
    int e = threadIdx.x;
    if (e >= E_TOT) return;
    const int nodeOf[E_TOT] = {0,1,1,2,2,2,3,3,3,3};
    const int iOf[E_TOT]    = {0,0,1,0,1,2,0,1,2,3};
    int node = nodeOf[e], i = iOf[e];
    float norm = en[node * 5 + i];
    norm = fmaxf(norm, 1e-5f);           // clip, STRENGTH=1.0 -> norm^1
    float lg[12];
    float m = -1e30f;
    #pragma unroll
    for (int k = 0; k < 12; k++) {
        lg[k] = ap[(node * 5 + i) * 12 + k] / norm;
        m = fmaxf(m, lg[k]);
    }
    float s = 0.f;
    #pragma unroll
    for (int k = 0; k < 12; k++) { lg[k] = expf(lg[k] - m); s += lg[k]; }
    float inv = 1.0f / s;
    #pragma unroll
    for (int k = 0; k < 12; k++) g_w[e][k] = lg[k] * inv;
}

// ---------------------------------------------------------------------------
// Kernel 2: build the fused effective 9x9 kernel per edge.
//   All linear branches collapse: conv3/5/7/1, sep3 (pw*dw), sep5, dil3, dil5,
//   and w0 * identity (center delta at co==ci).
//   grid (e, ci), 64 threads = co.  Writes coalesced in co.
// ---------------------------------------------------------------------------
__global__ void keff_kernel(const float* __restrict__ w3p,  const float* __restrict__ w5p,
                            const float* __restrict__ w7p,  const float* __restrict__ w1p,
                            const float* __restrict__ s3dw, const float* __restrict__ s3pw,
                            const float* __restrict__ s5dw, const float* __restrict__ s5pw,
                            const float* __restrict__ d3p,  const float* __restrict__ d5p) {
    int e  = blockIdx.x;
    int ci = blockIdx.y;
    int co = threadIdx.x;
    const float* wv = g_w[e];

    float k[81];
    #pragma unroll
    for (int t = 0; t < 81; t++) k[t] = 0.f;

    int oc  = (e * P_CH + co) * P_CH + ci;   // OIHW index base (o=co, i=ci)
    int dwc = e * P_CH + ci;                 // depthwise index base

    // conv3 (pad 1): offsets -1..1
    #pragma unroll
    for (int a = 0; a < 3; a++)
        #pragma unroll
        for (int b = 0; b < 3; b++)
            k[(3 + a) * 9 + (3 + b)] += wv[1] * w3p[oc * 9 + a * 3 + b];
    // conv5 (pad 2)
    #pragma unroll
    for (int a = 0; a < 5; a++)
        #pragma unroll
        for (int b = 0; b < 5; b++)
            k[(2 + a) * 9 + (2 + b)] += wv[2] * w5p[oc * 25 + a * 5 + b];
    // conv7 (pad 3)
    #pragma unroll
    for (int a = 0; a < 7; a++)
        #pragma unroll
        for (int b = 0; b < 7; b++)
            k[(1 + a) * 9 + (1 + b)] += wv[3] * w7p[oc * 49 + a * 7 + b];
    // conv1
    k[40] += wv[4] * w1p[oc];
    // identity
    if (co == ci) k[40] += wv[0];
    // sep3: pw[o,i] * dw[i, a, b]
    {
        float pw = s3pw[oc];
        #pragma unroll
        for (int a = 0; a < 3; a++)
            #pragma unroll
            for (int b = 0; b < 3; b++)
                k[(3 + a) * 9 + (3 + b)] += wv[7] * pw * s3dw[dwc * 9 + a * 3 + b];
    }
    // sep5
    {
        float pw = s5pw[oc];
        #pragma unroll
        for (int a = 0; a < 5; a++)
            #pragma unroll
            for (int b = 0; b < 5; b++)
                k[(2 + a) * 9 + (2 + b)] += wv[8] * pw * s5dw[dwc * 25 + a * 5 + b];
    }
    // dil3 (pad 2, dil 2): offsets 2*(a-1) in {-2,0,2}
    #pragma unroll
    for (int a = 0; a < 3; a++)
        #pragma unroll
        for (int b = 0; b < 3; b++)
            k[(2 + 2 * a) * 9 + (2 + 2 * b)] += wv[9] * d3p[oc * 9 + a * 3 + b];
    // dil5 (pad 4, dil 2): offsets 2*(a-2) in {-4..4}
    #pragma unroll
    for (int a = 0; a < 5; a++)
        #pragma unroll
        for (int b = 0; b < 5; b++)
            k[(2 * a) * 9 + (2 * b)] += wv[10] * d5p[oc * 25 + a * 5 + b];

    #pragma unroll
    for (int t = 0; t < 81; t++)
        g_keff[e][ci][t][co] = k[t];
}

// ---------------------------------------------------------------------------
// Kernel 3: pooling contribution:  acc (+)= w5*maxpool3(s) + w6*avgpool3(s)
//   over the FULL 256 channels.  first=1 -> overwrite (avoids zero-init pass).
// ---------------------------------------------------------------------------
__global__ void pool_kernel(const float* __restrict__ s, float* __restrict__ acc,
                            int e, int first) {
    int idx = blockIdx.x * 256 + threadIdx.x;       // < 64*256*1024
    float w5 = g_w[e][5];
    float w6 = g_w[e][6];
    int x = idx & 31;
    int y = (idx >> 5) & 31;
    const float* im = s + (idx & ~1023);
    float mx = -1e30f, sm = 0.f;
    #pragma unroll
    for (int dy = -1; dy <= 1; dy++) {
        int yy = y + dy;
        if ((unsigned)yy < 32u) {
            #pragma unroll
            for (int dx = -1; dx <= 1; dx++) {
                int xx = x + dx;
                if ((unsigned)xx < 32u) {
                    float v = im[yy * 32 + xx];
                    mx = fmaxf(mx, v);
                    sm += v;
                }
            }
        }
    }
    float r = w5 * mx + w6 * (sm * (1.0f / 9.0f));
    if (first) acc[idx] = r;
    else       acc[idx] += r;
}

// ---------------------------------------------------------------------------
// Kernel 4: fused 64ch -> 64ch effective-9x9 conv with channel gather/scatter.
//   grid (n=64, coTile=8), 256 threads.
//   thread: 2 consecutive co x 16-px row segment.  ci staged 8 at a time.
//   Only the 65 non-identically-zero taps are evaluated.
// ---------------------------------------------------------------------------
#define SIN_ELEMS (8 * 40 * 41)      // 13120 (41-padded rows -> conflict-free)
#define SW_ELEMS  (8 * 81 * 8)       // 5184
#define CONV_SMEM_BYTES ((SIN_ELEMS + SW_ELEMS) * 4 + 64 * 4)

#define TAP(DXI) {                                                        \
    const int t_ = dyi * 9 + (DXI);                                       \
    float w0v = wC[t_ * 8];                                               \
    float w1v = wC[t_ * 8 + 1];                                           \
    _Pragma("unroll")                                                     \
    for (int p = 0; p < 16; p++) {                                        \
        float v = rin[p + (DXI)];                                         \
        a0[p] = fmaf(w0v, v, a0[p]);                                      \
        a1[p] = fmaf(w1v, v, a1[p]);                                      \
    } }

__global__ void __launch_bounds__(256, 2)
conv_kernel(const float* __restrict__ s, float* __restrict__ acc,
            const int* __restrict__ ids, int e) {
    extern __shared__ float smem[];
    float* sIn = smem;                       // [8][40][41]
    float* sW  = smem + SIN_ELEMS;           // [8][81][8]
    int*  sIds = (int*)(smem + SIN_ELEMS + SW_ELEMS);

    int n      = blockIdx.x;
    int coTile = blockIdx.y;                 // 0..7 (8 co each)
    int tid    = threadIdx.x;

    if (tid < 64) sIds[tid] = ids[tid];
    __syncthreads();

    int g   = tid >> 6;                      // 0..3 -> 2 co each
    int sp  = tid & 63;
    int row = sp >> 1;                       // 0..31
    int xt  = (sp & 1) << 4;                 // 0 or 16

    float a0[16], a1[16];
    #pragma unroll
    for (int p = 0; p < 16; p++) { a0[p] = 0.f; a1[p] = 0.f; }

    const float* sBase = s + (size_t)n * C_FULL * SPAT;

    for (int cc = 0; cc < 8; cc++) {
        // stage 8 gathered input channels with 4-wide zero halo
        for (int idx = tid; idx < SIN_ELEMS; idx += 256) {
            int ci = idx / 1640;
            int r  = idx - ci * 1640;
            int yy = r / 41;
            int xx = r - yy * 41;
            float v = 0.f;
            int gy = yy - 4, gx = xx - 4;
            if (xx < 40 && (unsigned)gy < 32u && (unsigned)gx < 32u)
                v = sBase[sIds[cc * 8 + ci] * SPAT + gy * 32 + gx];
            sIn[idx] = v;
        }
        // stage weights for these 8 ci x 8 co
        for (int idx = tid; idx < SW_ELEMS; idx += 256) {
            int ci = idx / 648;
            int r  = idx - ci * 648;
            int t  = r >> 3;
            int co = r & 7;
            sW[idx] = g_keff[e][cc * 8 + ci][t][coTile * 8 + co];
        }
        __syncthreads();

        #pragma unroll 1
        for (int ci = 0; ci < 8; ci++) {
            const float* inC = sIn + ci * 1640;
            const float* wC  = sW + ci * 648 + g * 2;
            #pragma unroll 1
            for (int dyi = 0; dyi < 9; dyi++) {
                const float* inRow = inC + (row + dyi) * 41 + xt;
                float rin[24];
                #pragma unroll
                for (int kk = 0; kk < 24; kk++) rin[kk] = inRow[kk];
                if (dyi == 0 || dyi == 8) {
                    // dy = +-4: only even dx taps (dil5)
                    TAP(0) TAP(2) TAP(4) TAP(6) TAP(8)
                } else if (dyi & 1) {
                    // dy odd: |dx| <= 3
                    TAP(1) TAP(2) TAP(3) TAP(4) TAP(5) TAP(6) TAP(7)
                } else {
                    // dy in {-2,0,2}: all dx
                    TAP(0) TAP(1) TAP(2) TAP(3) TAP(4) TAP(5) TAP(6) TAP(7) TAP(8)
                }
            }
        }
        __syncthreads();
    }

    // scatter-accumulate into acc channels ids[co]
    int co0 = coTile * 8 + g * 2;
    int c0 = sIds[co0];
    int c1 = sIds[co0 + 1];
    float* o0 = acc + ((size_t)n * C_FULL + c0) * SPAT + row * 32 + xt;
    float* o1 = acc + ((size_t)n * C_FULL + c1) * SPAT + row * 32 + xt;
    #pragma unroll
    for (int p = 0; p < 16; p++) o0[p] += a0[p];
    #pragma unroll
    for (int p = 0; p < 16; p++) o1[p] += a1[p];
}

// ---------------------------------------------------------------------------
extern "C" void kernel_launch(void* const* d_in, const int* in_sizes, int n_in,
                              void* d_out, int out_size) {
    const float* x    = (const float*)d_in[0];
    const float* ap   = (const float*)d_in[1];
    const float* en   = (const float*)d_in[2];
    const int*   idx  = (const int*)  d_in[3];
    const float* w3   = (const float*)d_in[4];
    const float* w5   = (const float*)d_in[5];
    const float* w7   = (const float*)d_in[6];
    const float* w1   = (const float*)d_in[7];
    const float* s3dw = (const float*)d_in[8];
    const float* s3pw = (const float*)d_in[9];
    const float* s5dw = (const float*)d_in[10];
    const float* s5pw = (const float*)d_in[11];
    const float* d3   = (const float*)d_in[12];
    const float* d5   = (const float*)d_in[13];
    float* out = (float*)d_out;

    cudaFuncSetAttribute(conv_kernel, cudaFuncAttributeMaxDynamicSharedMemorySize,
                         CONV_SMEM_BYTES);

    float* st0 = nullptr;
    cudaGetSymbolAddress((void**)&st0, g_state);

    softmax_kernel<<<1, 32>>>(ap, en);
    keff_kernel<<<dim3(E_TOT, P_CH), P_CH>>>(w3, w5, w7, w1, s3dw, s3pw,
                                             s5dw, s5pw, d3, d5);

    int e = 0;
    for (int node = 0; node < 4; node++) {
        float* acc = (node < 3) ? (st0 + (size_t)node * STATE_SZ) : out;
        for (int i = 0; i <= node; i++) {
            const float* s = (i == 0) ? x : (st0 + (size_t)(i - 1) * STATE_SZ);
            // first edge of a node overwrites acc (no zero-init pass needed)
            pool_kernel<<<STATE_SZ / 256, 256>>>(s, acc, e, (i == 0) ? 1 : 0);
            conv_kernel<<<dim3(N_BATCH, 8), 256, CONV_SMEM_BYTES>>>(
                s, acc, idx + e * 64, e);
            e++;
        }
    }
}

// round 7
// speedup vs baseline: 1.2318x; 1.2318x over previous
#include <cuda_runtime.h>
#include <math.h>

// Problem constants
#define N_BATCH 64
#define C_FULL  256
#define P_CH    64
#define HW      32
#define SPAT    1024            // 32*32
#define E_TOT   10
#define STATE_SZ (N_BATCH * C_FULL * SPAT)   // 16,777,216 floats

// Persistent device scratch (no allocation allowed in kernel_launch)
__device__ float g_state[3][STATE_SZ];              // states 1..3 (state 4 -> d_out)
__device__ float g_keff[E_TOT][8][P_CH][81][8];     // [e][coTile][ci][tap][co8]
__device__ float g_w[E_TOT][12];                    // softmaxed arch weights

// ---------------------------------------------------------------------------
// Kernel 1: softmax of arch params per edge
// ---------------------------------------------------------------------------
__global__ void softmax_kernel(const float* __restrict__ ap,
                               const float* __restrict__ en) {
    int e = threadIdx.x;
    if (e >= E_TOT) return;
    const int nodeOf[E_TOT] = {0,1,1,2,2,2,3,3,3,3};
    const int iOf[E_TOT]    = {0,0,1,0,1,2,0,1,2,3};
    int node = nodeOf[e], i = iOf[e];
    float norm = en[node * 5 + i];
    norm = fmaxf(norm, 1e-5f);           // clip, STRENGTH=1.0 -> norm^1
    float lg[12];
    float m = -1e30f;
    #pragma unroll
    for (int k = 0; k < 12; k++) {
        lg[k] = ap[(node * 5 + i) * 12 + k] / norm;
        m = fmaxf(m, lg[k]);
    }
    float s = 0.f;
    #pragma unroll
    for (int k = 0; k < 12; k++) { lg[k] = expf(lg[k] - m); s += lg[k]; }
    float inv = 1.0f / s;
    #pragma unroll
    for (int k = 0; k < 12; k++) g_w[e][k] = lg[k] * inv;
}

// ---------------------------------------------------------------------------
// Kernel 2: build the fused effective 9x9 kernel per edge.
//   All linear branches collapse: conv3/5/7/1, sep3 (pw*dw), sep5, dil3, dil5,
//   and w0 * identity (center delta at co==ci).
//   Stored transposed: [e][coTile][ci][tap][co8] so the conv kernel's weight
//   staging is one contiguous float4 memcpy per (cc, coTile).
// ---------------------------------------------------------------------------
__global__ void keff_kernel(const float* __restrict__ w3p,  const float* __restrict__ w5p,
                            const float* __restrict__ w7p,  const float* __restrict__ w1p,
                            const float* __restrict__ s3dw, const float* __restrict__ s3pw,
                            const float* __restrict__ s5dw, const float* __restrict__ s5pw,
                            const float* __restrict__ d3p,  const float* __restrict__ d5p) {
    int e  = blockIdx.x;
    int ci = blockIdx.y;
    int co = threadIdx.x;
    const float* wv = g_w[e];

    float k[81];
    #pragma unroll
    for (int t = 0; t < 81; t++) k[t] = 0.f;

    int oc  = (e * P_CH + co) * P_CH + ci;   // OIHW index base (o=co, i=ci)
    int dwc = e * P_CH + ci;                 // depthwise index base

    // conv3 (pad 1)
    #pragma unroll
    for (int a = 0; a < 3; a++)
        #pragma unroll
        for (int b = 0; b < 3; b++)
            k[(3 + a) * 9 + (3 + b)] += wv[1] * w3p[oc * 9 + a * 3 + b];
    // conv5 (pad 2)
    #pragma unroll
    for (int a = 0; a < 5; a++)
        #pragma unroll
        for (int b = 0; b < 5; b++)
            k[(2 + a) * 9 + (2 + b)] += wv[2] * w5p[oc * 25 + a * 5 + b];
    // conv7 (pad 3)
    #pragma unroll
    for (int a = 0; a < 7; a++)
        #pragma unroll
        for (int b = 0; b < 7; b++)
            k[(1 + a) * 9 + (1 + b)] += wv[3] * w7p[oc * 49 + a * 7 + b];
    // conv1
    k[40] += wv[4] * w1p[oc];
    // identity
    if (co == ci) k[40] += wv[0];
    // sep3: pw[o,i] * dw[i,a,b]
    {
        float pw = s3pw[oc];
        #pragma unroll
        for (int a = 0; a < 3; a++)
            #pragma unroll
            for (int b = 0; b < 3; b++)
                k[(3 + a) * 9 + (3 + b)] += wv[7] * pw * s3dw[dwc * 9 + a * 3 + b];
    }
    // sep5
    {
        float pw = s5pw[oc];
        #pragma unroll
        for (int a = 0; a < 5; a++)
            #pragma unroll
            for (int b = 0; b < 5; b++)
                k[(2 + a) * 9 + (2 + b)] += wv[8] * pw * s5dw[dwc * 25 + a * 5 + b];
    }
    // dil3 (pad 2, dil 2)
    #pragma unroll
    for (int a = 0; a < 3; a++)
        #pragma unroll
        for (int b = 0; b < 3; b++)
            k[(2 + 2 * a) * 9 + (2 + 2 * b)] += wv[9] * d3p[oc * 9 + a * 3 + b];
    // dil5 (pad 4, dil 2)
    #pragma unroll
    for (int a = 0; a < 5; a++)
        #pragma unroll
        for (int b = 0; b < 5; b++)
            k[(2 * a) * 9 + (2 * b)] += wv[10] * d5p[oc * 25 + a * 5 + b];

    #pragma unroll
    for (int t = 0; t < 81; t++)
        g_keff[e][co >> 3][ci][t][co & 7] = k[t];
}

// ---------------------------------------------------------------------------
// Kernel 3: pooling contribution:  acc (+)= w5*maxpool3(s) + w6*avgpool3(s)
//   over the FULL 256 channels.  first=1 -> overwrite (avoids zero-init pass).
// ---------------------------------------------------------------------------
__global__ void pool_kernel(const float* __restrict__ s, float* __restrict__ acc,
                            int e, int first) {
    int idx = blockIdx.x * 256 + threadIdx.x;       // < 64*256*1024
    float w5 = g_w[e][5];
    float w6 = g_w[e][6];
    int x = idx & 31;
    int y = (idx >> 5) & 31;
    const float* im = s + (idx & ~1023);
    float mx = -1e30f, sm = 0.f;
    #pragma unroll
    for (int dy = -1; dy <= 1; dy++) {
        int yy = y + dy;
        if ((unsigned)yy < 32u) {
            #pragma unroll
            for (int dx = -1; dx <= 1; dx++) {
                int xx = x + dx;
                if ((unsigned)xx < 32u) {
                    float v = im[yy * 32 + xx];
                    mx = fmaxf(mx, v);
                    sm += v;
                }
            }
        }
    }
    float r = w5 * mx + w6 * (sm * (1.0f / 9.0f));
    if (first) acc[idx] = r;
    else       acc[idx] += r;
}

// ---------------------------------------------------------------------------
// Kernel 4: fused 64ch -> 64ch effective-9x9 conv with channel gather/scatter.
//   grid (n=64, coTile=8), 256 threads; thread = 2 co x 16-px row segment.
//   ci staged 8 at a time.  Stride-44 rows: 16B-aligned LDS.128, conflict-free
//   (per 8-lane phase, banks 12r+16(l&1) mod 32 cover all 32 banks).
//   Halo zeros written ONCE; per-cc staging touches only the 32x32 interior
//   via LDG.128/STS.128 (no integer divides).
// ---------------------------------------------------------------------------
#define SW_IN     44
#define CH_ELEMS  (40 * SW_IN)               // 1760
#define SIN_ELEMS (8 * CH_ELEMS)             // 14080
#define SW_ELEMS  (8 * 81 * 8)               // 5184
#define CONV_SMEM_BYTES ((SIN_ELEMS + SW_ELEMS) * 4 + 64 * 4)

#define TAP(DXI) {                                                        \
    float2 wv2 = *(const float2*)(wC + (dyi * 9 + (DXI)) * 8 + g2);       \
    _Pragma("unroll")                                                     \
    for (int p = 0; p < 16; p++) {                                        \
        float v = rin[p + (DXI)];                                         \
        a0[p] = fmaf(wv2.x, v, a0[p]);                                    \
        a1[p] = fmaf(wv2.y, v, a1[p]);                                    \
    } }

__global__ void __launch_bounds__(256, 2)
conv_kernel(const float* __restrict__ s, float* __restrict__ acc,
            const int* __restrict__ ids, int e) {
    extern __shared__ float smem[];
    float* sIn = smem;                       // [8][40][44]
    float* sW  = smem + SIN_ELEMS;           // [8][81][8]
    int*  sIds = (int*)(smem + SIN_ELEMS + SW_ELEMS);

    int n      = blockIdx.x;
    int coTile = blockIdx.y;                 // 0..7 (8 co each)
    int tid    = threadIdx.x;

    if (tid < 64) sIds[tid] = ids[tid];
    // Zero the whole input slab once; halo stays zero, interior is
    // overwritten each cc.
    {
        float4 z = make_float4(0.f, 0.f, 0.f, 0.f);
        for (int i = tid; i < SIN_ELEMS / 4; i += 256)
            ((float4*)sIn)[i] = z;
    }
    __syncthreads();

    int g   = tid >> 6;                      // 0..3 -> 2 co each
    int g2  = g * 2;
    int sp  = tid & 63;
    int row = sp >> 1;                       // 0..31
    int xt  = (sp & 1) << 4;                 // 0 or 16

    int ldRow = tid >> 3;                    // 0..31 (staging row)
    int ldX4  = tid & 7;                     // 0..7  (staging float4 col)

    float a0[16], a1[16];
    #pragma unroll
    for (int p = 0; p < 16; p++) { a0[p] = 0.f; a1[p] = 0.f; }

    const float* sBase = s + (size_t)n * C_FULL * SPAT;
    const float* wSrc  = &g_keff[e][coTile][0][0][0];   // [64][81][8] contiguous

    for (int cc = 0; cc < 8; cc++) {
        // stage interior of 8 gathered channels: 1 LDG.128+STS.128 per ci/thread
        #pragma unroll
        for (int ci = 0; ci < 8; ci++) {
            const float4* src =
                (const float4*)(sBase + (size_t)sIds[cc * 8 + ci] * SPAT + ldRow * 32)
                + ldX4;
            float4 v = *src;
            *((float4*)(sIn + ci * CH_ELEMS + (ldRow + 4) * SW_IN + 4) + ldX4) = v;
        }
        // stage weights: contiguous 5184-float block -> float4 memcpy
        {
            const float4* w4 = (const float4*)(wSrc + cc * SW_ELEMS);
            for (int i = tid; i < SW_ELEMS / 4; i += 256)
                ((float4*)sW)[i] = w4[i];
        }
        __syncthreads();

        #pragma unroll 1
        for (int ci = 0; ci < 8; ci++) {
            const float* inC = sIn + ci * CH_ELEMS;
            const float* wC  = sW + ci * 648;
            #pragma unroll 1
            for (int dyi = 0; dyi < 9; dyi++) {
                const float4* pr = (const float4*)(inC + (row + dyi) * SW_IN + xt);
                float rin[24];
                #pragma unroll
                for (int kk = 0; kk < 6; kk++)
                    ((float4*)rin)[kk] = pr[kk];
                if (dyi == 0 || dyi == 8) {
                    // dy = +-4: only even dx taps (dil5)
                    TAP(0) TAP(2) TAP(4) TAP(6) TAP(8)
                } else if (dyi & 1) {
                    // dy odd: |dx| <= 3
                    TAP(1) TAP(2) TAP(3) TAP(4) TAP(5) TAP(6) TAP(7)
                } else {
                    // dy in {-2,0,2}: all dx
                    TAP(0) TAP(1) TAP(2) TAP(3) TAP(4) TAP(5) TAP(6) TAP(7) TAP(8)
                }
            }
        }
        __syncthreads();
    }

    // scatter-accumulate into acc channels ids[co], vectorized RMW
    int co0 = coTile * 8 + g2;
    float* o0 = acc + ((size_t)n * C_FULL + sIds[co0])     * SPAT + row * 32 + xt;
    float* o1 = acc + ((size_t)n * C_FULL + sIds[co0 + 1]) * SPAT + row * 32 + xt;
    #pragma unroll
    for (int q = 0; q < 4; q++) {
        float4 v = ((float4*)o0)[q];
        v.x += a0[q * 4 + 0]; v.y += a0[q * 4 + 1];
        v.z += a0[q * 4 + 2]; v.w += a0[q * 4 + 3];
        ((float4*)o0)[q] = v;
    }
    #pragma unroll
    for (int q = 0; q < 4; q++) {
        float4 v = ((float4*)o1)[q];
        v.x += a1[q * 4 + 0]; v.y += a1[q * 4 + 1];
        v.z += a1[q * 4 + 2]; v.w += a1[q * 4 + 3];
        ((float4*)o1)[q] = v;
    }
}

// ---------------------------------------------------------------------------
extern "C" void kernel_launch(void* const* d_in, const int* in_sizes, int n_in,
                              void* d_out, int out_size) {
    const float* x    = (const float*)d_in[0];
    const float* ap   = (const float*)d_in[1];
    const float* en   = (const float*)d_in[2];
    const int*   idx  = (const int*)  d_in[3];
    const float* w3   = (const float*)d_in[4];
    const float* w5   = (const float*)d_in[5];
    const float* w7   = (const float*)d_in[6];
    const float* w1   = (const float*)d_in[7];
    const float* s3dw = (const float*)d_in[8];
    const float* s3pw = (const float*)d_in[9];
    const float* s5dw = (const float*)d_in[10];
    const float* s5pw = (const float*)d_in[11];
    const float* d3   = (const float*)d_in[12];
    const float* d5   = (const float*)d_in[13];
    float* out = (float*)d_out;

    cudaFuncSetAttribute(conv_kernel, cudaFuncAttributeMaxDynamicSharedMemorySize,
                         CONV_SMEM_BYTES);

    float* st0 = nullptr;
    cudaGetSymbolAddress((void**)&st0, g_state);

    softmax_kernel<<<1, 32>>>(ap, en);
    keff_kernel<<<dim3(E_TOT, P_CH), P_CH>>>(w3, w5, w7, w1, s3dw, s3pw,
                                             s5dw, s5pw, d3, d5);

    int e = 0;
    for (int node = 0; node < 4; node++) {
        float* acc = (node < 3) ? (st0 + (size_t)node * STATE_SZ) : out;
        for (int i = 0; i <= node; i++) {
            const float* s = (i == 0) ? x : (st0 + (size_t)(i - 1) * STATE_SZ);
            // first edge of a node overwrites acc (no zero-init pass needed)
            pool_kernel<<<STATE_SZ / 256, 256>>>(s, acc, e, (i == 0) ? 1 : 0);
            conv_kernel<<<dim3(N_BATCH, 8), 256, CONV_SMEM_BYTES>>>(
                s, acc, idx + e * 64, e);
            e++;
        }
    }
}